// round 14
// baseline (speedup 1.0000x reference)
#include <cuda_runtime.h>
#include <cstdint>

// B=8, M=512, A=16, F=128. Dense register-resident contraction:
//   out[d,f] = sum_c y[c,f] * ( sum_a cgc[a,d,c] * x[a,f] )
// d-PACKED coefficients: one LDS.128 = 4 coefficients ({d0,d1} x 2 a's).
// x duplicated {x,x} into persistent regs per warp-tile; dp split in 2 passes;
// explicit A/B coefficient double-buffer. 3 blocks/SM (regs<=170) with a
// global atomic tile queue for near-perfect load balance.

#define AA 16
#define TILE_FLOATS 2048
#define THREADS 128
#define GRID_BLOCKS 444            // 148 SMs x 3 blocks

typedef unsigned long long ull;

__device__ int g_tile_ctr;

__global__ void tp_reset_ctr() { g_tile_ctr = 0; }

__device__ __forceinline__ ull fma2(ull a, ull b, ull c) {
    ull d;
    asm("fma.rn.f32x2 %0, %1, %2, %3;" : "=l"(d) : "l"(a), "l"(b), "l"(c));
    return d;
}
__device__ __forceinline__ ull dup32(float v) {
    unsigned int u = __float_as_uint(v);
    return ((ull)u << 32) | u;
}
__device__ __forceinline__ float ulo(ull v) { return __uint_as_float((unsigned int)v); }
__device__ __forceinline__ float uhi(ull v) { return __uint_as_float((unsigned int)(v >> 32)); }

// load a 4-entry coefficient group (4 x LDS.128)
#define LOADQ(buf, base)            \
    {                               \
        buf[0] = gc[(base) + 0];    \
        buf[1] = gc[(base) + 1];    \
        buf[2] = gc[(base) + 2];    \
        buf[3] = gc[(base) + 3];    \
    }

// 32 FFMA2 consuming one 4-entry group; ab = a-base (0 or 8)
#define FMAG(buf, ab)                                       \
    {                                                       \
        _Pragma("unroll")                                   \
        for (int q = 0; q < 4; ++q) {                       \
            const ulonglong2 gg = buf[q];                   \
            const int a0 = ((ab) + q * 2) * 4;              \
            const int a1 = ((ab) + q * 2 + 1) * 4;          \
            t0 = fma2(gg.x, xd[a0 + 0], t0);                \
            t1 = fma2(gg.x, xd[a0 + 1], t1);                \
            t2 = fma2(gg.x, xd[a0 + 2], t2);                \
            t3 = fma2(gg.x, xd[a0 + 3], t3);                \
            t0 = fma2(gg.y, xd[a1 + 0], t0);                \
            t1 = fma2(gg.y, xd[a1 + 1], t1);                \
            t2 = fma2(gg.y, xd[a1 + 2], t2);                \
            t3 = fma2(gg.y, xd[a1 + 3], t3);                \
        }                                                   \
    }

// fold t into acc for local d-pair dpl, then reset t
#define ACCUM(dpl)                                              \
    {                                                           \
        acc[(dpl) * 4 + 0] = fma2(t0, yd0, acc[(dpl) * 4 + 0]); \
        acc[(dpl) * 4 + 1] = fma2(t1, yd1, acc[(dpl) * 4 + 1]); \
        acc[(dpl) * 4 + 2] = fma2(t2, yd2, acc[(dpl) * 4 + 2]); \
        acc[(dpl) * 4 + 3] = fma2(t3, yd3, acc[(dpl) * 4 + 3]); \
        t0 = t1 = t2 = t3 = 0ull;                               \
    }

__global__ __launch_bounds__(THREADS, 3) void tp_dense_kernel(
    const float* __restrict__ x,
    const float* __restrict__ y,
    const float* __restrict__ cgc,
    float* __restrict__ out,
    int n_bm)
{
    // Staged cgc, d-pair packed: gdpk[c][dp][a] = {g[a,2dp,c], g[a,2dp+1,c]}
    __shared__ float sc[AA * AA * AA];          // 16 KB linear copy
    __shared__ __align__(16) ull gdpk[2048];    // 16 KB packed

    const int tid = threadIdx.x;

#pragma unroll
    for (int j = tid; j < AA * AA * AA; j += THREADS) sc[j] = cgc[j];
    __syncthreads();
#pragma unroll
    for (int s = tid; s < 2048; s += THREADS) {
        const int c  = s >> 7;
        const int dp = (s >> 4) & 7;
        const int a  = s & 15;
        const unsigned int lo = __float_as_uint(sc[a * 256 + dp * 32 + c]);
        const unsigned int hi = __float_as_uint(sc[a * 256 + dp * 32 + 16 + c]);
        gdpk[s] = ((ull)hi << 32) | lo;
    }
    __syncthreads();

    const int lane = tid & 31;

    // Dynamic tile queue: each warp grabs the next tile index.
    for (;;) {
        int bm;
        if (lane == 0) bm = atomicAdd(&g_tile_ctr, 1);
        bm = __shfl_sync(0xFFFFFFFFu, bm, 0);
        if (bm >= n_bm) break;

        const float4* xg4 = (const float4*)(x + (size_t)bm * TILE_FLOATS);
        const float4* yg4 = (const float4*)(y + (size_t)bm * TILE_FLOATS);
        float4*       og4 = (float4*)(out + (size_t)bm * TILE_FLOATS);

        // x tile -> duplicated regs (persists across both dp passes)
        ull xd[AA * 4];
#pragma unroll
        for (int a = 0; a < AA; ++a) {
            const float4 xv = xg4[a * 32 + lane];
            xd[a * 4 + 0] = dup32(xv.x);
            xd[a * 4 + 1] = dup32(xv.y);
            xd[a * 4 + 2] = dup32(xv.z);
            xd[a * 4 + 3] = dup32(xv.w);
        }

#pragma unroll 1
        for (int pass = 0; pass < 2; ++pass) {
            const int dbase = pass * 4;   // dp base for this pass

            ull acc[16];
#pragma unroll
            for (int i = 0; i < 16; ++i) acc[i] = 0ull;

            float4 yv = yg4[lane];

#pragma unroll 1
            for (int c = 0; c < AA; ++c) {
                const ull yd0 = dup32(yv.x);
                const ull yd1 = dup32(yv.y);
                const ull yd2 = dup32(yv.z);
                const ull yd3 = dup32(yv.w);
                yv = yg4[((c + 1) & 15) * 32 + lane];   // prefetch next c

                const ulonglong2* gc =
                    (const ulonglong2*)(gdpk + c * 128 + dbase * 16);

                ulonglong2 bufA[4], bufB[4];
                ull t0 = 0ull, t1 = 0ull, t2 = 0ull, t3 = 0ull;

                // software pipeline: load group g+1 while FMAing group g
                LOADQ(bufA, 0);
                LOADQ(bufB, 4);   FMAG(bufA, 0);
                LOADQ(bufA, 8);   FMAG(bufB, 8);  ACCUM(0);
                LOADQ(bufB, 12);  FMAG(bufA, 0);
                LOADQ(bufA, 16);  FMAG(bufB, 8);  ACCUM(1);
                LOADQ(bufB, 20);  FMAG(bufA, 0);
                LOADQ(bufA, 24);  FMAG(bufB, 8);  ACCUM(2);
                LOADQ(bufB, 28);  FMAG(bufA, 0);
                                  FMAG(bufB, 8);  ACCUM(3);
            }

            // Epilogue: unpack d-pairs -> two float4 rows per dp
#pragma unroll
            for (int dpl = 0; dpl < 4; ++dpl) {
                const int dp = dbase + dpl;
                const float4 o0 = make_float4(
                    ulo(acc[dpl * 4 + 0]), ulo(acc[dpl * 4 + 1]),
                    ulo(acc[dpl * 4 + 2]), ulo(acc[dpl * 4 + 3]));
                const float4 o1 = make_float4(
                    uhi(acc[dpl * 4 + 0]), uhi(acc[dpl * 4 + 1]),
                    uhi(acc[dpl * 4 + 2]), uhi(acc[dpl * 4 + 3]));
                og4[(dp * 2) * 32 + lane]     = o0;
                og4[(dp * 2 + 1) * 32 + lane] = o1;
            }
        }
    }
}

extern "C" void kernel_launch(void* const* d_in, const int* in_sizes, int n_in,
                              void* d_out, int out_size) {
    const float* x   = (const float*)d_in[0];
    const float* y   = (const float*)d_in[1];
    const float* cgc = (const float*)d_in[2];
    float* out = (float*)d_out;

    const int n_bm = in_sizes[0] / TILE_FLOATS;   // 4096

    tp_reset_ctr<<<1, 1>>>();
    tp_dense_kernel<<<GRID_BLOCKS, THREADS>>>(x, y, cgc, out, n_bm);
}